// round 13
// baseline (speedup 1.0000x reference)
#include <cuda_runtime.h>
#include <cuda_fp16.h>
#include <stdint.h>
#include <math.h>

#define B_ 2
#define S_ 4096
#define D_ 1024
#define H_ 16
#define HD_ 64
#define M_ 512
#define L_ 1024
#define HID_ 2816
#define NSTEP 8

// ---------------- scratch (static device globals; no allocs) ----------------
__device__ __align__(16) __half g_wqkvTh[3*D_*D_], g_wqkvTl[3*D_*D_];
__device__ __align__(16) __half g_w13Th [2*HID_*D_], g_w13Tl [2*HID_*D_];
__device__ __align__(16) __half g_wkvmTh[2*D_*D_], g_wkvmTl[2*D_*D_];
__device__ __align__(16) __half g_wmTh  [D_*D_],  g_wmTl  [D_*D_];
__device__ __align__(16) __half g_w2Th  [D_*HID_], g_w2Tl [D_*HID_];
__device__ __align__(16) __half g_woTh  [D_*D_],  g_woTl  [D_*D_];
__device__ __align__(16) __half g_xh [B_*S_*D_],  g_xl [B_*S_*D_];
__device__ __align__(16) __half g_omh[B_*M_*D_],  g_oml[B_*M_*D_];
__device__ __align__(16) __half g_th [B_*M_*D_],  g_tl [B_*M_*D_];
__device__ __align__(16) __half g_om3h[B_*M_*D_], g_om3l[B_*M_*D_];
__device__ __align__(16) __half g_gh [B_*M_*HID_], g_gl [B_*M_*HID_];
__device__ __align__(16) __half g_outh[B_*S_*D_], g_outl[B_*S_*D_];
__device__ float g_xqkv [B_*S_*3*D_];
__device__ float g_qall [NSTEP*B_*H_*M_*HD_];
__device__ float g_kxall[NSTEP*B_*H_*M_*HD_];
__device__ float g_vxall[NSTEP*B_*H_*M_*HD_];
__device__ float g_om2  [B_*M_*D_];
__device__ float g_hbuf [B_*M_*2*HID_];
__device__ float g_kvtmp[B_*M_*2*D_];
__device__ float g_kmem [B_*H_*M_*HD_], g_vmem[B_*H_*M_*HD_];

// ---------------- helpers ----------------------------------------------------
__device__ __forceinline__ void splith(float v, __half& h, __half& l) {
    h = __float2half_rn(v);
    l = __float2half_rn((v - __half2float(h)) * 2048.0f);
}

__device__ __forceinline__ void hmma(float* c, const uint32_t* a, const uint32_t* b)
{
    asm volatile("mma.sync.aligned.m16n8k16.row.col.f32.f16.f16.f32 "
                 "{%0,%1,%2,%3}, {%4,%5,%6,%7}, {%8,%9}, {%0,%1,%2,%3};"
                 : "+f"(c[0]), "+f"(c[1]), "+f"(c[2]), "+f"(c[3])
                 : "r"(a[0]), "r"(a[1]), "r"(a[2]), "r"(a[3]), "r"(b[0]), "r"(b[1]));
}

__device__ __forceinline__ void cpa16(uint8_t* dst, const void* src) {
    unsigned d = (unsigned)__cvta_generic_to_shared(dst);
    asm volatile("cp.async.cg.shared.global [%0], [%1], 16;" :: "r"(d), "l"(src));
}

__device__ __forceinline__ void ldm4(uint32_t* r, uint32_t addr) {
    asm volatile("ldmatrix.sync.aligned.m8n8.x4.shared.b16 {%0,%1,%2,%3}, [%4];"
                 : "=r"(r[0]), "=r"(r[1]), "=r"(r[2]), "=r"(r[3]) : "r"(addr));
}

// ---------------- fp16-split tensor GEMM (mma.sync + ldmatrix, 3-stage) ------
// C[M,Ntot] = (Ah + Al/2048) @ (Bh + Bl/2048)^T
// CTA tile 128x128, BK=32 halves, 256 threads (8 warps 4x2), warp tile 32x64.
#define HBM 128
#define HBN 128
#define HBK 32
#define ROWB 80            // bytes per smem row (32 halves + 8 pad)
#define STG_AH 0
#define STG_AL 10240
#define STG_BH 20480
#define STG_BL 30720
#define STG_SZ 40960
#define HSM_BYTES (3 * STG_SZ)

__global__ void __launch_bounds__(256, 1)
gemm_hs(const __half* __restrict__ Ah, const __half* __restrict__ Al,
        const __half* __restrict__ Bh, const __half* __restrict__ Bl,
        float* __restrict__ C, int Ntot, int K, int accum)
{
    extern __shared__ uint8_t dyn[];
    const uint32_t sb = (uint32_t)__cvta_generic_to_shared(dyn);
    const int tid = threadIdx.x, lane = tid & 31, wid = tid >> 5;
    const int grp = lane >> 2, qk = lane & 3;
    const int wm = (wid >> 1) * 32, wn = (wid & 1) * 64;
    const int bm0 = blockIdx.y * HBM, bn0 = blockIdx.x * HBN;

    // ldmatrix lane-address components
    const int aRow = (lane & 7) + ((lane >> 3) & 1) * 8;
    const int aCol = ((lane >> 4) & 1) * 16;
    const int bRow = (lane & 7) + ((lane >> 4) & 1) * 8;
    const int bCol = ((lane >> 3) & 1) * 16;

    float acc0[2][8][4], acc1[2][8][4];
#pragma unroll
    for (int i = 0; i < 2; i++)
#pragma unroll
        for (int j = 0; j < 8; j++)
#pragma unroll
            for (int e = 0; e < 4; e++) { acc0[i][j][e] = 0.f; acc1[i][j][e] = 0.f; }

    auto issue = [&](int ci) {
        int p = ci % 3;
        int k0 = ci * HBK;
        uint8_t* dAh = dyn + p * STG_SZ + STG_AH;
        uint8_t* dAl = dyn + p * STG_SZ + STG_AL;
        uint8_t* dBh = dyn + p * STG_SZ + STG_BH;
        uint8_t* dBl = dyn + p * STG_SZ + STG_BL;
#pragma unroll
        for (int i = 0; i < 2; i++) {
            int idx = tid + i * 256;            // 512 chunks of 16B (A)
            int row = idx >> 2, c16 = idx & 3;
            size_t go = (size_t)(bm0 + row) * K + k0 + c16 * 8;
            cpa16(dAh + row * ROWB + c16 * 16, Ah + go);
            cpa16(dAl + row * ROWB + c16 * 16, Al + go);
        }
#pragma unroll
        for (int i = 0; i < 2; i++) {
            int idx = tid + i * 256;            // 512 chunks of 16B (B)
            int row = idx >> 2, c16 = idx & 3;
            size_t go = (size_t)(bn0 + row) * K + k0 + c16 * 8;
            cpa16(dBh + row * ROWB + c16 * 16, Bh + go);
            cpa16(dBl + row * ROWB + c16 * 16, Bl + go);
        }
        asm volatile("cp.async.commit_group;");
    };

    const int nch = K / HBK;
    issue(0);
    if (nch > 1) issue(1);

    for (int st = 0; st < nch; st++) {
        if (st + 1 < nch) {
            asm volatile("cp.async.wait_group 1;");
        } else {
            asm volatile("cp.async.wait_group 0;");
        }
        __syncthreads();
        if (st + 2 < nch) issue(st + 2);

        int p = st % 3;
        uint32_t base = sb + p * STG_SZ;
#pragma unroll
        for (int s16 = 0; s16 < 2; s16++) {
            const int cb0 = s16 * 32;
            uint32_t ah[2][4], al[2][4], bh[8][2], bl[8][2];
#pragma unroll
            for (int mt = 0; mt < 2; mt++) {
                uint32_t ad = base + STG_AH + (wm + mt * 16 + aRow) * ROWB + cb0 + aCol;
                ldm4(ah[mt], ad);
                ldm4(al[mt], ad + (STG_AL - STG_AH));
            }
#pragma unroll
            for (int g = 0; g < 4; g++) {
                uint32_t tmp[4];
                uint32_t bd = base + STG_BH + (wn + g * 16 + bRow) * ROWB + cb0 + bCol;
                ldm4(tmp, bd);
                bh[2 * g][0] = tmp[0]; bh[2 * g][1] = tmp[1];
                bh[2 * g + 1][0] = tmp[2]; bh[2 * g + 1][1] = tmp[3];
                ldm4(tmp, bd + (STG_BL - STG_BH));
                bl[2 * g][0] = tmp[0]; bl[2 * g][1] = tmp[1];
                bl[2 * g + 1][0] = tmp[2]; bl[2 * g + 1][1] = tmp[3];
            }
#pragma unroll
            for (int mt = 0; mt < 2; mt++)
#pragma unroll
                for (int nt = 0; nt < 8; nt++) {
                    hmma(acc0[mt][nt], ah[mt], bh[nt]);
                    hmma(acc1[mt][nt], ah[mt], bl[nt]);
                    hmma(acc1[mt][nt], al[mt], bh[nt]);
                }
        }
    }

    const float isc = 4.8828125e-4f;   // 1/2048
#pragma unroll
    for (int mt = 0; mt < 2; mt++) {
        int r0 = bm0 + wm + mt * 16 + grp;
#pragma unroll
        for (int nt = 0; nt < 8; nt++) {
            int c0 = bn0 + wn + nt * 8 + 2 * qk;
            float v0 = acc0[mt][nt][0] + acc1[mt][nt][0] * isc;
            float v1 = acc0[mt][nt][1] + acc1[mt][nt][1] * isc;
            float v2 = acc0[mt][nt][2] + acc1[mt][nt][2] * isc;
            float v3 = acc0[mt][nt][3] + acc1[mt][nt][3] * isc;
            float2* p0 = (float2*)(C + (size_t)r0 * Ntot + c0);
            float2* p1 = (float2*)(C + (size_t)(r0 + 8) * Ntot + c0);
            float2 w0 = make_float2(v0, v1), w1 = make_float2(v2, v3);
            if (accum) {
                float2 o0 = *p0, o1 = *p1;
                w0.x += o0.x; w0.y += o0.y; w1.x += o1.x; w1.y += o1.y;
            }
            *p0 = w0;
            *p1 = w1;
        }
    }
}

// ---------------- weight transpose + split: w[K][N] -> out[N][K] -------------
__global__ void __launch_bounds__(256) wsplitT(const float* __restrict__ w,
                                               __half* __restrict__ bh,
                                               __half* __restrict__ bl,
                                               int K, int N)
{
    __shared__ float t[32][33];
    int n0 = blockIdx.x * 32, k0 = blockIdx.y * 32;
    int tx = threadIdx.x & 31, ty = threadIdx.x >> 5;
#pragma unroll
    for (int i = 0; i < 4; i++)
        t[ty + i * 8][tx] = w[(size_t)(k0 + ty + i * 8) * N + n0 + tx];
    __syncthreads();
#pragma unroll
    for (int i = 0; i < 4; i++) {
        int nn = ty + i * 8;
        float v = t[tx][nn];
        __half h, l;
        splith(v, h, l);
        bh[(size_t)(n0 + nn) * K + k0 + tx] = h;
        bl[(size_t)(n0 + nn) * K + k0 + tx] = l;
    }
}

// ---------------- activation split (no transpose) ----------------------------
__global__ void __launch_bounds__(256) asplit(const float* __restrict__ in,
                                              __half* __restrict__ oh,
                                              __half* __restrict__ ol, int n4)
{
    int i = blockIdx.x * 256 + threadIdx.x;
    if (i >= n4) return;
    float4 v = ((const float4*)in)[i];
    __half h0, l0, h1, l1, h2, l2, h3, l3;
    splith(v.x, h0, l0); splith(v.y, h1, l1);
    splith(v.z, h2, l2); splith(v.w, h3, l3);
    ((__half2*)oh)[i * 2]     = __halves2half2(h0, h1);
    ((__half2*)oh)[i * 2 + 1] = __halves2half2(h2, h3);
    ((__half2*)ol)[i * 2]     = __halves2half2(l0, l1);
    ((__half2*)ol)[i * 2 + 1] = __halves2half2(l2, l3);
}

__global__ void __launch_bounds__(256) init_om_split(const float* __restrict__ om0)
{
    int t = blockIdx.x * 256 + threadIdx.x;     // 2*512*1024
    int d = t & 1023;
    int i = (t >> 10) & 511;
    __half h, l;
    splith(om0[i * 1024 + d], h, l);
    g_omh[t] = h; g_oml[t] = l;
}

// ---------------- rmsnorm -> split -------------------------------------------
__global__ void __launch_bounds__(256) rmsnorm_split(const float* __restrict__ in,
                                                     const float* __restrict__ w,
                                                     __half* __restrict__ oh,
                                                     __half* __restrict__ ol)
{
    const int row = blockIdx.x;
    const int t = threadIdx.x;
    float4 v = ((const float4*)(in + (size_t)row * D_))[t];
    float ss = v.x * v.x + v.y * v.y + v.z * v.z + v.w * v.w;
#pragma unroll
    for (int o = 16; o; o >>= 1) ss += __shfl_xor_sync(0xffffffffu, ss, o);
    __shared__ float sred[8];
    if ((t & 31) == 0) sred[t >> 5] = ss;
    __syncthreads();
    float tot = 0.f;
#pragma unroll
    for (int i = 0; i < 8; i++) tot += sred[i];
    float rs = rsqrtf(tot * (1.0f / (float)D_) + 1e-5f);
    float4 wv = ((const float4*)w)[t];
    float y0 = v.x * rs * wv.x, y1 = v.y * rs * wv.y;
    float y2 = v.z * rs * wv.z, y3 = v.w * rs * wv.w;
    __half h0, l0, h1, l1, h2, l2, h3, l3;
    splith(y0, h0, l0); splith(y1, h1, l1); splith(y2, h2, l2); splith(y3, h3, l3);
    __half2* ph = (__half2*)(oh + (size_t)row * D_);
    __half2* pl = (__half2*)(ol + (size_t)row * D_);
    ph[t * 2]     = __halves2half2(h0, h1);
    ph[t * 2 + 1] = __halves2half2(h2, h3);
    pl[t * 2]     = __halves2half2(l0, l1);
    pl[t * 2 + 1] = __halves2half2(l2, l3);
}

// ---------------- silu -> split ----------------------------------------------
__global__ void __launch_bounds__(256) silu_split(const float* __restrict__ hb,
                                                  __half* __restrict__ gh,
                                                  __half* __restrict__ gl)
{
    int c4 = blockIdx.x * 256 + threadIdx.x;     // 0..703
    if (c4 >= HID_ / 4) return;
    int row = blockIdx.y;
    const float* rp = hb + (size_t)row * (2 * HID_);
    float4 a = ((const float4*)rp)[c4];
    float4 b = ((const float4*)(rp + HID_))[c4];
    float g0 = a.x / (1.f + __expf(-a.x)) * b.x;
    float g1 = a.y / (1.f + __expf(-a.y)) * b.y;
    float g2 = a.z / (1.f + __expf(-a.z)) * b.z;
    float g3 = a.w / (1.f + __expf(-a.w)) * b.w;
    __half h0, l0, h1, l1, h2, l2, h3, l3;
    splith(g0, h0, l0); splith(g1, h1, l1); splith(g2, h2, l2); splith(g3, h3, l3);
    __half2* ph = (__half2*)(gh + (size_t)row * HID_);
    __half2* pl = (__half2*)(gl + (size_t)row * HID_);
    ph[c4 * 2]     = __halves2half2(h0, h1);
    ph[c4 * 2 + 1] = __halves2half2(h2, h3);
    pl[c4 * 2]     = __halves2half2(l0, l1);
    pl[c4 * 2 + 1] = __halves2half2(l2, l3);
}

// ---------------- rope / scatter ---------------------------------------------
__global__ void __launch_bounds__(256) rope_all(const float* __restrict__ fcos,
                                                const float* __restrict__ fsin,
                                                float* __restrict__ out, int colOff)
{
    int t = blockIdx.x * 256 + threadIdx.x;      // 4194304
    int j = t & 31;
    int h = (t >> 5) & 15;
    int rowg = t >> 9;
    int i = rowg & 511;
    int s = (rowg >> 9) & 7;
    int b = rowg >> 12;
    int pos = M_ + i;
    float c = fcos[pos * 32 + j];
    float sn = fsin[pos * 32 + j];
    float2 v = *(const float2*)(g_xqkv + (size_t)rowg * 3072 + colOff + h * 64 + 2 * j);
    float2 o;
    o.x = v.x * c - v.y * sn;
    o.y = v.x * sn + v.y * c;
    *(float2*)(out + (size_t)s * (B_*H_*M_*HD_) + (((size_t)(b * 16 + h) * 512 + i) * 64 + 2 * j)) = o;
}

__global__ void __launch_bounds__(256) scatter_all_v()
{
    int t = blockIdx.x * 256 + threadIdx.x;      // 2097152
    int f = t & 255;
    int h = f >> 4, d4 = f & 15;
    int rowg = t >> 8;
    int i = rowg & 511;
    int s = (rowg >> 9) & 7;
    int b = rowg >> 12;
    float4 v = ((const float4*)g_xqkv)[(size_t)rowg * 768 + 512 + f];
    ((float4*)g_vxall)[(size_t)s * (B_*H_*M_*HD_/4) + ((size_t)(b * 16 + h) * 512 + i) * 16 + d4] = v;
}

__global__ void __launch_bounds__(256) rope_mem(const float* __restrict__ fcos,
                                                const float* __restrict__ fsin)
{
    int t = blockIdx.x * 256 + threadIdx.x;      // 524288
    int j = t & 31;
    int h = (t >> 5) & 15;
    int rowg = t >> 9;
    int i = rowg & 511;
    int b = rowg >> 9;
    float c = fcos[i * 32 + j];
    float sn = fsin[i * 32 + j];
    float2 v = *(const float2*)(g_kvtmp + (size_t)rowg * 2048 + h * 64 + 2 * j);
    float2 o;
    o.x = v.x * c - v.y * sn;
    o.y = v.x * sn + v.y * c;
    *(float2*)(g_kmem + ((size_t)(b * 16 + h) * 512 + i) * 64 + 2 * j) = o;
}

__global__ void __launch_bounds__(256) scatter_vmem()
{
    int t = blockIdx.x * 256 + threadIdx.x;      // 262144
    int f = t & 255;
    int h = f >> 4, d4 = f & 15;
    int rowg = t >> 8;
    int i = rowg & 511;
    int b = rowg >> 9;
    float4 v = ((const float4*)g_kvtmp)[(size_t)rowg * 512 + 256 + f];
    ((float4*)g_vmem)[((size_t)(b * 16 + h) * 512 + i) * 16 + d4] = v;
}

// ---------------- fused causal attention (x queries only) --------------------
__global__ void __launch_bounds__(128) attn2(const float* __restrict__ Qs,
                                             const float* __restrict__ Kx,
                                             const float* __restrict__ Vx,
                                             int stepOff)
{
    __shared__ float Ksh[64 * 72];
    __shared__ float Vsh[64 * 72];
    const int bh = blockIdx.x;
    const int by = blockIdx.y;
    const int b = bh >> 4, h = bh & 15;
    const int tid = threadIdx.x;
    const int rl = tid >> 1;
    const int half = tid & 1;
    const int off = half * 36;
    const int qrow = by * 64 + rl;

    const float* qp = Qs + ((size_t)bh * 512 + qrow) * 64 + half * 32;
    float q[32];
#pragma unroll
    for (int d = 0; d < 32; d += 4) {
        float4 v = *(const float4*)(qp + d);
        q[d] = v.x; q[d + 1] = v.y; q[d + 2] = v.z; q[d + 3] = v.w;
    }
    float O[32];
#pragma unroll
    for (int d = 0; d < 32; d++) O[d] = 0.f;
    float m = -1e30f, l = 0.f;

    const int nkt = 9 + by;
    for (int kt = 0; kt < nkt; kt++) {
        const float* ksrc = (kt < 8) ? (g_kmem + ((size_t)bh * 512 + kt * 64) * 64)
                                     : (Kx + ((size_t)bh * 512 + (kt - 8) * 64) * 64);
        const float* vsrc = (kt < 8) ? (g_vmem + ((size_t)bh * 512 + kt * 64) * 64)
                                     : (Vx + ((size_t)bh * 512 + (kt - 8) * 64) * 64);
        __syncthreads();
#pragma unroll
        for (int i = 0; i < 8; i++) {
            int idx = i * 128 + tid;
            int row = idx >> 4, c4 = idx & 15;
            int dst = row * 72 + c4 * 4 + (c4 >= 8 ? 4 : 0);
            *(float4*)(Ksh + dst) = ((const float4*)ksrc)[idx];
            *(float4*)(Vsh + dst) = ((const float4*)vsrc)[idx];
        }
        __syncthreads();
        const bool diag = (kt == 8 + by);
#pragma unroll 1
        for (int c = 0; c < 4; c++) {
            float sreg[16];
            float mt = -1e30f;
#pragma unroll
            for (int j = 0; j < 16; j++) {
                const float* kr = Ksh + (c * 16 + j) * 72 + off;
                float p = 0.f;
#pragma unroll
                for (int d = 0; d < 32; d += 4) {
                    float4 k4 = *(const float4*)(kr + d);
                    p += q[d] * k4.x + q[d + 1] * k4.y + q[d + 2] * k4.z + q[d + 3] * k4.w;
                }
                p += __shfl_xor_sync(0xffffffffu, p, 1);
                float sj = p * 0.125f;
                if (diag && (c * 16 + j) > rl) sj = -1e30f;
                sreg[j] = sj;
                mt = fmaxf(mt, sj);
            }
            float mnew = fmaxf(m, mt);
            float corr = __expf(m - mnew);
            l *= corr;
#pragma unroll
            for (int d = 0; d < 32; d++) O[d] *= corr;
#pragma unroll
            for (int j = 0; j < 16; j++) {
                float pj = __expf(sreg[j] - mnew);
                l += pj;
                const float* vr = Vsh + (c * 16 + j) * 72 + off;
#pragma unroll
                for (int d = 0; d < 32; d += 4) {
                    float4 v4 = *(const float4*)(vr + d);
                    O[d]     += pj * v4.x;
                    O[d + 1] += pj * v4.y;
                    O[d + 2] += pj * v4.z;
                    O[d + 3] += pj * v4.w;
                }
            }
            m = mnew;
        }
    }

    float inv = 1.0f / l;
    size_t o1 = ((size_t)b * S_ + stepOff + qrow) * D_ + h * 64 + half * 32;
    size_t o2 = ((size_t)(b * 512 + qrow)) * D_ + h * 64 + half * 32;
#pragma unroll
    for (int d = 0; d < 32; d += 2) {
        float v0 = O[d] * inv, v1 = O[d + 1] * inv;
        __half h0, l0, h1, l1;
        splith(v0, h0, l0);
        splith(v1, h1, l1);
        __half2 hh = __halves2half2(h0, h1);
        __half2 ll = __halves2half2(l0, l1);
        *(__half2*)(g_outh + o1 + d) = hh;
        *(__half2*)(g_outl + o1 + d) = ll;
        *(__half2*)(g_omh + o2 + d) = hh;
        *(__half2*)(g_oml + o2 + d) = ll;
    }
}

// ---------------- host driver ------------------------------------------------
static void* symp(const void* s) { void* p; cudaGetSymbolAddress(&p, s); return p; }

extern "C" void kernel_launch(void* const* d_in, const int* in_sizes, int n_in,
                              void* d_out, int out_size)
{
    (void)in_sizes; (void)n_in; (void)out_size;
    const float* x    = (const float*)d_in[0];
    const float* fcos = (const float*)d_in[1];
    const float* fsin = (const float*)d_in[2];
    const float* wq   = (const float*)d_in[3];
    const float* wk   = (const float*)d_in[4];
    const float* wv   = (const float*)d_in[5];
    const float* wo   = (const float*)d_in[6];
    const float* wm   = (const float*)d_in[7];
    const float* wkm  = (const float*)d_in[8];
    const float* wvm  = (const float*)d_in[9];
    const float* w1   = (const float*)d_in[10];
    const float* w3   = (const float*)d_in[11];
    const float* w2   = (const float*)d_in[12];
    const float* ffnw = (const float*)d_in[13];
    const float* memw = (const float*)d_in[14];
    const float* om0  = (const float*)d_in[15];
    float* outp = (float*)d_out;

    static bool attrDone = false;
    if (!attrDone) {
        cudaFuncSetAttribute(gemm_hs, cudaFuncAttributeMaxDynamicSharedMemorySize, HSM_BYTES);
        attrDone = true;
    }

    __half *wqkvTh = (__half*)symp(g_wqkvTh), *wqkvTl = (__half*)symp(g_wqkvTl);
    __half *w13Th = (__half*)symp(g_w13Th), *w13Tl = (__half*)symp(g_w13Tl);
    __half *wkvmTh = (__half*)symp(g_wkvmTh), *wkvmTl = (__half*)symp(g_wkvmTl);
    __half *wmTh = (__half*)symp(g_wmTh), *wmTl = (__half*)symp(g_wmTl);
    __half *w2Th = (__half*)symp(g_w2Th), *w2Tl = (__half*)symp(g_w2Tl);
    __half *woTh = (__half*)symp(g_woTh), *woTl = (__half*)symp(g_woTl);
    __half *xh = (__half*)symp(g_xh), *xl = (__half*)symp(g_xl);
    __half *omh = (__half*)symp(g_omh), *oml = (__half*)symp(g_oml);
    __half *th = (__half*)symp(g_th), *tl = (__half*)symp(g_tl);
    __half *om3h = (__half*)symp(g_om3h), *om3l = (__half*)symp(g_om3l);
    __half *gh = (__half*)symp(g_gh), *gl = (__half*)symp(g_gl);
    __half *outh = (__half*)symp(g_outh), *outl = (__half*)symp(g_outl);
    float *xqkv = (float*)symp(g_xqkv);
    float *qall = (float*)symp(g_qall), *kxall = (float*)symp(g_kxall), *vxall = (float*)symp(g_vxall);
    float *om2 = (float*)symp(g_om2), *hbuf = (float*)symp(g_hbuf);
    float *kvtmp = (float*)symp(g_kvtmp);

    // ---- weight transpose+split / input split (per launch) ----
    wsplitT<<<dim3(32, 32), 256>>>(wq, wqkvTh, wqkvTl, 1024, 1024);
    wsplitT<<<dim3(32, 32), 256>>>(wk, wqkvTh + 1024 * 1024, wqkvTl + 1024 * 1024, 1024, 1024);
    wsplitT<<<dim3(32, 32), 256>>>(wv, wqkvTh + 2048 * 1024, wqkvTl + 2048 * 1024, 1024, 1024);
    wsplitT<<<dim3(88, 32), 256>>>(w1, w13Th, w13Tl, 1024, 2816);
    wsplitT<<<dim3(88, 32), 256>>>(w3, w13Th + 2816 * 1024, w13Tl + 2816 * 1024, 1024, 2816);
    wsplitT<<<dim3(32, 32), 256>>>(wkm, wkvmTh, wkvmTl, 1024, 1024);
    wsplitT<<<dim3(32, 32), 256>>>(wvm, wkvmTh + 1024 * 1024, wkvmTl + 1024 * 1024, 1024, 1024);
    wsplitT<<<dim3(32, 32), 256>>>(wm, wmTh, wmTl, 1024, 1024);
    wsplitT<<<dim3(32, 88), 256>>>(w2, w2Th, w2Tl, 2816, 1024);
    wsplitT<<<dim3(32, 32), 256>>>(wo, woTh, woTl, 1024, 1024);
    asplit<<<8192, 256>>>(x, xh, xl, B_ * S_ * D_ / 4);
    init_om_split<<<4096, 256>>>(om0);

    // ---- batched x-branch ----
    gemm_hs<<<dim3(24, 64), 256, HSM_BYTES>>>(xh, xl, wqkvTh, wqkvTl, xqkv, 3072, 1024, 0);
    rope_all<<<16384, 256>>>(fcos, fsin, qall, 0);
    rope_all<<<16384, 256>>>(fcos, fsin, kxall, 1024);
    scatter_all_v<<<8192, 256>>>();

    const size_t stepSz = (size_t)B_ * H_ * M_ * HD_;
    for (int s = 0; s < NSTEP; s++) {
        gemm_hs<<<dim3(8, 8), 256, HSM_BYTES>>>(omh, oml, wmTh, wmTl, om2, 1024, 1024, 0);
        rmsnorm_split<<<1024, 256>>>(om2, ffnw, th, tl);
        gemm_hs<<<dim3(44, 8), 256, HSM_BYTES>>>(th, tl, w13Th, w13Tl, hbuf, 5632, 1024, 0);
        silu_split<<<dim3(3, 1024), 256>>>(hbuf, gh, gl);
        gemm_hs<<<dim3(8, 8), 256, HSM_BYTES>>>(gh, gl, w2Th, w2Tl, om2, 1024, 2816, 1);
        rmsnorm_split<<<1024, 256>>>(om2, memw, om3h, om3l);
        gemm_hs<<<dim3(16, 8), 256, HSM_BYTES>>>(om3h, om3l, wkvmTh, wkvmTl, kvtmp, 2048, 1024, 0);
        rope_mem<<<2048, 256>>>(fcos, fsin);
        scatter_vmem<<<1024, 256>>>();
        attn2<<<dim3(B_ * H_, 8), 128>>>(qall + s * stepSz, kxall + s * stepSz,
                                         vxall + s * stepSz, s * M_);
    }

    // ---- final projection ----
    gemm_hs<<<dim3(8, 64), 256, HSM_BYTES>>>(outh, outl, woTh, woTl, outp, 1024, 1024, 0);
}

// round 14
// speedup vs baseline: 1.1750x; 1.1750x over previous
#include <cuda_runtime.h>
#include <cuda_fp16.h>
#include <stdint.h>
#include <math.h>

#define B_ 2
#define S_ 4096
#define D_ 1024
#define H_ 16
#define HD_ 64
#define M_ 512
#define L_ 1024
#define HID_ 2816
#define NSTEP 8

// ---------------- scratch (static device globals; no allocs) ----------------
__device__ __align__(16) __half g_wqkvTh[3*D_*D_], g_wqkvTl[3*D_*D_];
__device__ __align__(16) __half g_w13Th [2*HID_*D_], g_w13Tl [2*HID_*D_]; // interleaved rows
__device__ __align__(16) __half g_wkvmTh[2*D_*D_], g_wkvmTl[2*D_*D_];
__device__ __align__(16) __half g_wmTh  [D_*D_],  g_wmTl  [D_*D_];
__device__ __align__(16) __half g_w2Th  [D_*HID_], g_w2Tl [D_*HID_];
__device__ __align__(16) __half g_woTh  [D_*D_],  g_woTl  [D_*D_];
__device__ __align__(16) __half g_xh [B_*S_*D_],  g_xl [B_*S_*D_];
__device__ __align__(16) __half g_omh[B_*M_*D_],  g_oml[B_*M_*D_];
__device__ __align__(16) __half g_th [B_*M_*D_],  g_tl [B_*M_*D_];
__device__ __align__(16) __half g_om3h[B_*M_*D_], g_om3l[B_*M_*D_];
__device__ __align__(16) __half g_gh [B_*M_*HID_], g_gl [B_*M_*HID_];
__device__ __align__(16) __half g_outh[B_*S_*D_], g_outl[B_*S_*D_];
__device__ float g_qall [NSTEP*B_*H_*M_*HD_];
__device__ float g_kxall[NSTEP*B_*H_*M_*HD_];
__device__ float g_vxall[NSTEP*B_*H_*M_*HD_];
__device__ float g_om2  [B_*M_*D_];
__device__ float g_kmem [B_*H_*M_*HD_], g_vmem[B_*H_*M_*HD_];

// ---------------- helpers ----------------------------------------------------
__device__ __forceinline__ void splith(float v, __half& h, __half& l) {
    h = __float2half_rn(v);
    l = __float2half_rn((v - __half2float(h)) * 2048.0f);
}

__device__ __forceinline__ void hmma(float* c, const uint32_t* a, const uint32_t* b)
{
    asm volatile("mma.sync.aligned.m16n8k16.row.col.f32.f16.f16.f32 "
                 "{%0,%1,%2,%3}, {%4,%5,%6,%7}, {%8,%9}, {%0,%1,%2,%3};"
                 : "+f"(c[0]), "+f"(c[1]), "+f"(c[2]), "+f"(c[3])
                 : "r"(a[0]), "r"(a[1]), "r"(a[2]), "r"(a[3]), "r"(b[0]), "r"(b[1]));
}

__device__ __forceinline__ void cpa16(uint8_t* dst, const void* src) {
    unsigned d = (unsigned)__cvta_generic_to_shared(dst);
    asm volatile("cp.async.cg.shared.global [%0], [%1], 16;" :: "r"(d), "l"(src));
}

__device__ __forceinline__ void ldm4(uint32_t* r, uint32_t addr) {
    asm volatile("ldmatrix.sync.aligned.m8n8.x4.shared.b16 {%0,%1,%2,%3}, [%4];"
                 : "=r"(r[0]), "=r"(r[1]), "=r"(r[2]), "=r"(r[3]) : "r"(addr));
}

// ---------------- fp16-split tensor GEMM (mma.sync + ldmatrix, 3-stage) ------
// C[M,Ntot] = (Ah + Al/2048) @ (Bh + Bl/2048)^T
// CTA tile 128x64, BK=32 halves, 256 threads (8 warps 4x2), warp tile 32x32.
// Epilogue modes:
//   0 plain fp32 store   1 fp32 accum
//   2 silu-pair fuse: B rows interleaved (2n=w1,2n+1=w3) -> gh/gl halves
//   3 kvm rope fuse: cols<1024 rope->kmem, else scatter->vmem
//   4 xqkv rope fuse: q/k rope, v scatter -> qall/kxall/vxall (per-step layout)
#define HBM 128
#define HBN 64
#define HBK 32
#define ROWB 80
#define STG_AH 0
#define STG_AL 10240
#define STG_BH 20480
#define STG_BL 25600
#define STG_SZ 30720
#define HSM_BYTES (3 * STG_SZ)

__global__ void __launch_bounds__(256, 2)
gemm_hs(const __half* __restrict__ Ah, const __half* __restrict__ Al,
        const __half* __restrict__ Bh, const __half* __restrict__ Bl,
        float* __restrict__ C, int Ntot, int K, int mode,
        const float* __restrict__ fcos, const float* __restrict__ fsin,
        void* p0, void* p1, void* p2)
{
    extern __shared__ uint8_t dyn[];
    const uint32_t sb = (uint32_t)__cvta_generic_to_shared(dyn);
    const int tid = threadIdx.x, lane = tid & 31, wid = tid >> 5;
    const int grp = lane >> 2, qk = lane & 3;
    const int wm = (wid >> 1) * 32, wn = (wid & 1) * 32;
    const int bm0 = blockIdx.y * HBM, bn0 = blockIdx.x * HBN;

    const int aRow = (lane & 7) + ((lane >> 3) & 1) * 8;
    const int aCol = ((lane >> 4) & 1) * 16;
    const int bRow = (lane & 7) + ((lane >> 4) & 1) * 8;
    const int bCol = ((lane >> 3) & 1) * 16;

    float acc0[2][4][4], acc1[2][4][4];
#pragma unroll
    for (int i = 0; i < 2; i++)
#pragma unroll
        for (int j = 0; j < 4; j++)
#pragma unroll
            for (int e = 0; e < 4; e++) { acc0[i][j][e] = 0.f; acc1[i][j][e] = 0.f; }

    auto issue = [&](int ci) {
        int p = ci % 3;
        int k0 = ci * HBK;
        uint8_t* dAh = dyn + p * STG_SZ + STG_AH;
        uint8_t* dAl = dyn + p * STG_SZ + STG_AL;
        uint8_t* dBh = dyn + p * STG_SZ + STG_BH;
        uint8_t* dBl = dyn + p * STG_SZ + STG_BL;
#pragma unroll
        for (int i = 0; i < 2; i++) {
            int idx = tid + i * 256;
            int row = idx >> 2, c16 = idx & 3;
            size_t go = (size_t)(bm0 + row) * K + k0 + c16 * 8;
            cpa16(dAh + row * ROWB + c16 * 16, Ah + go);
            cpa16(dAl + row * ROWB + c16 * 16, Al + go);
        }
        {
            int row = tid >> 2, c16 = tid & 3;
            size_t go = (size_t)(bn0 + row) * K + k0 + c16 * 8;
            cpa16(dBh + row * ROWB + c16 * 16, Bh + go);
            cpa16(dBl + row * ROWB + c16 * 16, Bl + go);
        }
        asm volatile("cp.async.commit_group;");
    };

    const int nch = K / HBK;
    issue(0);
    if (nch > 1) issue(1);

    for (int st = 0; st < nch; st++) {
        if (st + 1 < nch) {
            asm volatile("cp.async.wait_group 1;");
        } else {
            asm volatile("cp.async.wait_group 0;");
        }
        __syncthreads();
        if (st + 2 < nch) issue(st + 2);

        int p = st % 3;
        uint32_t base = sb + p * STG_SZ;
#pragma unroll
        for (int s16 = 0; s16 < 2; s16++) {
            const int cb0 = s16 * 32;
            uint32_t ah[2][4], al[2][4], bh[4][2], bl[4][2];
#pragma unroll
            for (int mt = 0; mt < 2; mt++) {
                uint32_t ad = base + STG_AH + (wm + mt * 16 + aRow) * ROWB + cb0 + aCol;
                ldm4(ah[mt], ad);
                ldm4(al[mt], ad + (STG_AL - STG_AH));
            }
#pragma unroll
            for (int g = 0; g < 2; g++) {
                uint32_t tmp[4];
                uint32_t bd = base + STG_BH + (wn + g * 16 + bRow) * ROWB + cb0 + bCol;
                ldm4(tmp, bd);
                bh[2 * g][0] = tmp[0]; bh[2 * g][1] = tmp[1];
                bh[2 * g + 1][0] = tmp[2]; bh[2 * g + 1][1] = tmp[3];
                ldm4(tmp, bd + (STG_BL - STG_BH));
                bl[2 * g][0] = tmp[0]; bl[2 * g][1] = tmp[1];
                bl[2 * g + 1][0] = tmp[2]; bl[2 * g + 1][1] = tmp[3];
            }
#pragma unroll
            for (int mt = 0; mt < 2; mt++)
#pragma unroll
                for (int nt = 0; nt < 4; nt++) {
                    hmma(acc0[mt][nt], ah[mt], bh[nt]);
                    hmma(acc1[mt][nt], ah[mt], bl[nt]);
                    hmma(acc1[mt][nt], al[mt], bh[nt]);
                }
        }
    }

    const float isc = 4.8828125e-4f;   // 1/2048

    auto epi = [&](int r, int c, float u0, float u1) {
        if (mode == 0) {
            *(float2*)(C + (size_t)r * Ntot + c) = make_float2(u0, u1);
        } else if (mode == 1) {
            float2* p = (float2*)(C + (size_t)r * Ntot + c);
            float2 o = *p; o.x += u0; o.y += u1; *p = o;
        } else if (mode == 2) {
            int n = c >> 1;
            float g = u0 / (1.f + __expf(-u0)) * u1;
            __half hh, ll;
            splith(g, hh, ll);
            ((__half*)p0)[(size_t)r * HID_ + n] = hh;
            ((__half*)p1)[(size_t)r * HID_ + n] = ll;
        } else if (mode == 3) {
            int b = r >> 9, i = r & 511;
            if (c < 1024) {
                int h = c >> 6, j = (c & 63) >> 1;
                float cs = fcos[i * 32 + j], sn = fsin[i * 32 + j];
                float2 o = make_float2(u0 * cs - u1 * sn, u0 * sn + u1 * cs);
                *(float2*)((float*)p0 + (((size_t)(b * 16 + h) * 512 + i) * 64 + 2 * j)) = o;
            } else {
                int cc = c - 1024;
                int h = cc >> 6, d = cc & 63;
                *(float2*)((float*)p1 + (((size_t)(b * 16 + h) * 512 + i) * 64 + d)) = make_float2(u0, u1);
            }
        } else {  // mode 4
            int b = r >> 12, rem = r & 4095, s = rem >> 9, i = rem & 511;
            size_t so = (size_t)s * (B_ * H_ * M_ * HD_);
            if (c < 2048) {
                int cc = (c < 1024) ? c : c - 1024;
                int h = cc >> 6, j = (cc & 63) >> 1;
                int pos = M_ + i;
                float cs = fcos[pos * 32 + j], sn = fsin[pos * 32 + j];
                float2 o = make_float2(u0 * cs - u1 * sn, u0 * sn + u1 * cs);
                float* dst = (c < 1024) ? (float*)p0 : (float*)p1;
                *(float2*)(dst + so + (((size_t)(b * 16 + h) * 512 + i) * 64 + 2 * j)) = o;
            } else {
                int cc = c - 2048;
                int h = cc >> 6, d = cc & 63;
                *(float2*)((float*)p2 + so + (((size_t)(b * 16 + h) * 512 + i) * 64 + d)) = make_float2(u0, u1);
            }
        }
    };

#pragma unroll
    for (int mt = 0; mt < 2; mt++) {
        int r0 = bm0 + wm + mt * 16 + grp;
#pragma unroll
        for (int nt = 0; nt < 4; nt++) {
            int c0 = bn0 + wn + nt * 8 + 2 * qk;
            float v0 = acc0[mt][nt][0] + acc1[mt][nt][0] * isc;
            float v1 = acc0[mt][nt][1] + acc1[mt][nt][1] * isc;
            float v2 = acc0[mt][nt][2] + acc1[mt][nt][2] * isc;
            float v3 = acc0[mt][nt][3] + acc1[mt][nt][3] * isc;
            epi(r0, c0, v0, v1);
            epi(r0 + 8, c0, v2, v3);
        }
    }
}

// ---------------- weight transpose + split: w[K][N] -> out[n*rmul+roff][K] ---
__global__ void __launch_bounds__(256) wsplitT(const float* __restrict__ w,
                                               __half* __restrict__ bh,
                                               __half* __restrict__ bl,
                                               int K, int N, int rmul, int roff)
{
    __shared__ float t[32][33];
    int n0 = blockIdx.x * 32, k0 = blockIdx.y * 32;
    int tx = threadIdx.x & 31, ty = threadIdx.x >> 5;
#pragma unroll
    for (int i = 0; i < 4; i++)
        t[ty + i * 8][tx] = w[(size_t)(k0 + ty + i * 8) * N + n0 + tx];
    __syncthreads();
#pragma unroll
    for (int i = 0; i < 4; i++) {
        int nn = ty + i * 8;
        float v = t[tx][nn];
        __half h, l;
        splith(v, h, l);
        size_t drow = (size_t)(n0 + nn) * rmul + roff;
        bh[drow * K + k0 + tx] = h;
        bl[drow * K + k0 + tx] = l;
    }
}

// ---------------- activation split (no transpose) ----------------------------
__global__ void __launch_bounds__(256) asplit(const float* __restrict__ in,
                                              __half* __restrict__ oh,
                                              __half* __restrict__ ol, int n4)
{
    int i = blockIdx.x * 256 + threadIdx.x;
    if (i >= n4) return;
    float4 v = ((const float4*)in)[i];
    __half h0, l0, h1, l1, h2, l2, h3, l3;
    splith(v.x, h0, l0); splith(v.y, h1, l1);
    splith(v.z, h2, l2); splith(v.w, h3, l3);
    ((__half2*)oh)[i * 2]     = __halves2half2(h0, h1);
    ((__half2*)oh)[i * 2 + 1] = __halves2half2(h2, h3);
    ((__half2*)ol)[i * 2]     = __halves2half2(l0, l1);
    ((__half2*)ol)[i * 2 + 1] = __halves2half2(l2, l3);
}

__global__ void __launch_bounds__(256) init_om_split(const float* __restrict__ om0)
{
    int t = blockIdx.x * 256 + threadIdx.x;
    int d = t & 1023;
    int i = (t >> 10) & 511;
    __half h, l;
    splith(om0[i * 1024 + d], h, l);
    g_omh[t] = h; g_oml[t] = l;
}

// ---------------- rmsnorm -> split -------------------------------------------
__global__ void __launch_bounds__(256) rmsnorm_split(const float* __restrict__ in,
                                                     const float* __restrict__ w,
                                                     __half* __restrict__ oh,
                                                     __half* __restrict__ ol)
{
    const int row = blockIdx.x;
    const int t = threadIdx.x;
    float4 v = ((const float4*)(in + (size_t)row * D_))[t];
    float ss = v.x * v.x + v.y * v.y + v.z * v.z + v.w * v.w;
#pragma unroll
    for (int o = 16; o; o >>= 1) ss += __shfl_xor_sync(0xffffffffu, ss, o);
    __shared__ float sred[8];
    if ((t & 31) == 0) sred[t >> 5] = ss;
    __syncthreads();
    float tot = 0.f;
#pragma unroll
    for (int i = 0; i < 8; i++) tot += sred[i];
    float rs = rsqrtf(tot * (1.0f / (float)D_) + 1e-5f);
    float4 wv = ((const float4*)w)[t];
    float y0 = v.x * rs * wv.x, y1 = v.y * rs * wv.y;
    float y2 = v.z * rs * wv.z, y3 = v.w * rs * wv.w;
    __half h0, l0, h1, l1, h2, l2, h3, l3;
    splith(y0, h0, l0); splith(y1, h1, l1); splith(y2, h2, l2); splith(y3, h3, l3);
    __half2* ph = (__half2*)(oh + (size_t)row * D_);
    __half2* pl = (__half2*)(ol + (size_t)row * D_);
    ph[t * 2]     = __halves2half2(h0, h1);
    ph[t * 2 + 1] = __halves2half2(h2, h3);
    pl[t * 2]     = __halves2half2(l0, l1);
    pl[t * 2 + 1] = __halves2half2(l2, l3);
}

// ---------------- fused causal attention (x queries only) --------------------
__global__ void __launch_bounds__(128) attn2(const float* __restrict__ Qs,
                                             const float* __restrict__ Kx,
                                             const float* __restrict__ Vx,
                                             int stepOff)
{
    __shared__ float Ksh[64 * 72];
    __shared__ float Vsh[64 * 72];
    const int bh = blockIdx.x;
    const int by = blockIdx.y;
    const int b = bh >> 4, h = bh & 15;
    const int tid = threadIdx.x;
    const int rl = tid >> 1;
    const int half = tid & 1;
    const int off = half * 36;
    const int qrow = by * 64 + rl;

    const float* qp = Qs + ((size_t)bh * 512 + qrow) * 64 + half * 32;
    float q[32];
#pragma unroll
    for (int d = 0; d < 32; d += 4) {
        float4 v = *(const float4*)(qp + d);
        q[d] = v.x; q[d + 1] = v.y; q[d + 2] = v.z; q[d + 3] = v.w;
    }
    float O[32];
#pragma unroll
    for (int d = 0; d < 32; d++) O[d] = 0.f;
    float m = -1e30f, l = 0.f;

    const int nkt = 9 + by;
    for (int kt = 0; kt < nkt; kt++) {
        const float* ksrc = (kt < 8) ? (g_kmem + ((size_t)bh * 512 + kt * 64) * 64)
                                     : (Kx + ((size_t)bh * 512 + (kt - 8) * 64) * 64);
        const float* vsrc = (kt < 8) ? (g_vmem + ((size_t)bh * 512 + kt * 64) * 64)
                                     : (Vx + ((size_t)bh * 512 + (kt - 8) * 64) * 64);
        __syncthreads();
#pragma unroll
        for (int i = 0; i < 8; i++) {
            int idx = i * 128 + tid;
            int row = idx >> 4, c4 = idx & 15;
            int dst = row * 72 + c4 * 4 + (c4 >= 8 ? 4 : 0);
            *(float4*)(Ksh + dst) = ((const float4*)ksrc)[idx];
            *(float4*)(Vsh + dst) = ((const float4*)vsrc)[idx];
        }
        __syncthreads();
        const bool diag = (kt == 8 + by);
#pragma unroll 1
        for (int c = 0; c < 4; c++) {
            float sreg[16];
            float mt = -1e30f;
#pragma unroll
            for (int j = 0; j < 16; j++) {
                const float* kr = Ksh + (c * 16 + j) * 72 + off;
                float p = 0.f;
#pragma unroll
                for (int d = 0; d < 32; d += 4) {
                    float4 k4 = *(const float4*)(kr + d);
                    p += q[d] * k4.x + q[d + 1] * k4.y + q[d + 2] * k4.z + q[d + 3] * k4.w;
                }
                p += __shfl_xor_sync(0xffffffffu, p, 1);
                float sj = p * 0.125f;
                if (diag && (c * 16 + j) > rl) sj = -1e30f;
                sreg[j] = sj;
                mt = fmaxf(mt, sj);
            }
            float mnew = fmaxf(m, mt);
            float corr = __expf(m - mnew);
            l *= corr;
#pragma unroll
            for (int d = 0; d < 32; d++) O[d] *= corr;
#pragma unroll
            for (int j = 0; j < 16; j++) {
                float pj = __expf(sreg[j] - mnew);
                l += pj;
                const float* vr = Vsh + (c * 16 + j) * 72 + off;
#pragma unroll
                for (int d = 0; d < 32; d += 4) {
                    float4 v4 = *(const float4*)(vr + d);
                    O[d]     += pj * v4.x;
                    O[d + 1] += pj * v4.y;
                    O[d + 2] += pj * v4.z;
                    O[d + 3] += pj * v4.w;
                }
            }
            m = mnew;
        }
    }

    float inv = 1.0f / l;
    size_t o1 = ((size_t)b * S_ + stepOff + qrow) * D_ + h * 64 + half * 32;
    size_t o2 = ((size_t)(b * 512 + qrow)) * D_ + h * 64 + half * 32;
#pragma unroll
    for (int d = 0; d < 32; d += 2) {
        float v0 = O[d] * inv, v1 = O[d + 1] * inv;
        __half h0, l0, h1, l1;
        splith(v0, h0, l0);
        splith(v1, h1, l1);
        __half2 hh = __halves2half2(h0, h1);
        __half2 ll = __halves2half2(l0, l1);
        *(__half2*)(g_outh + o1 + d) = hh;
        *(__half2*)(g_outl + o1 + d) = ll;
        *(__half2*)(g_omh + o2 + d) = hh;
        *(__half2*)(g_oml + o2 + d) = ll;
    }
}

// ---------------- host driver ------------------------------------------------
static void* symp(const void* s) { void* p; cudaGetSymbolAddress(&p, s); return p; }

extern "C" void kernel_launch(void* const* d_in, const int* in_sizes, int n_in,
                              void* d_out, int out_size)
{
    (void)in_sizes; (void)n_in; (void)out_size;
    const float* x    = (const float*)d_in[0];
    const float* fcos = (const float*)d_in[1];
    const float* fsin = (const float*)d_in[2];
    const float* wq   = (const float*)d_in[3];
    const float* wk   = (const float*)d_in[4];
    const float* wv   = (const float*)d_in[5];
    const float* wo   = (const float*)d_in[6];
    const float* wm   = (const float*)d_in[7];
    const float* wkm  = (const float*)d_in[8];
    const float* wvm  = (const float*)d_in[9];
    const float* w1   = (const float*)d_in[10];
    const float* w3   = (const float*)d_in[11];
    const float* w2   = (const float*)d_in[12];
    const float* ffnw = (const float*)d_in[13];
    const float* memw = (const float*)d_in[14];
    const float* om0  = (const float*)d_in[15];
    float* outp = (float*)d_out;

    static bool attrDone = false;
    if (!attrDone) {
        cudaFuncSetAttribute(gemm_hs, cudaFuncAttributeMaxDynamicSharedMemorySize, HSM_BYTES);
        attrDone = true;
    }

    __half *wqkvTh = (__half*)symp(g_wqkvTh), *wqkvTl = (__half*)symp(g_wqkvTl);
    __half *w13Th = (__half*)symp(g_w13Th), *w13Tl = (__half*)symp(g_w13Tl);
    __half *wkvmTh = (__half*)symp(g_wkvmTh), *wkvmTl = (__half*)symp(g_wkvmTl);
    __half *wmTh = (__half*)symp(g_wmTh), *wmTl = (__half*)symp(g_wmTl);
    __half *w2Th = (__half*)symp(g_w2Th), *w2Tl = (__half*)symp(g_w2Tl);
    __half *woTh = (__half*)symp(g_woTh), *woTl = (__half*)symp(g_woTl);
    __half *xh = (__half*)symp(g_xh), *xl = (__half*)symp(g_xl);
    __half *omh = (__half*)symp(g_omh), *oml = (__half*)symp(g_oml);
    __half *th = (__half*)symp(g_th), *tl = (__half*)symp(g_tl);
    __half *om3h = (__half*)symp(g_om3h), *om3l = (__half*)symp(g_om3l);
    __half *gh = (__half*)symp(g_gh), *gl = (__half*)symp(g_gl);
    __half *outh = (__half*)symp(g_outh), *outl = (__half*)symp(g_outl);
    float *qall = (float*)symp(g_qall), *kxall = (float*)symp(g_kxall), *vxall = (float*)symp(g_vxall);
    float *om2 = (float*)symp(g_om2);
    float *kmem = (float*)symp(g_kmem), *vmem = (float*)symp(g_vmem);

    // ---- weight transpose+split / input split (per launch) ----
    wsplitT<<<dim3(32, 32), 256>>>(wq, wqkvTh, wqkvTl, 1024, 1024, 1, 0);
    wsplitT<<<dim3(32, 32), 256>>>(wk, wqkvTh + 1024 * 1024, wqkvTl + 1024 * 1024, 1024, 1024, 1, 0);
    wsplitT<<<dim3(32, 32), 256>>>(wv, wqkvTh + 2048 * 1024, wqkvTl + 2048 * 1024, 1024, 1024, 1, 0);
    wsplitT<<<dim3(88, 32), 256>>>(w1, w13Th, w13Tl, 1024, 2816, 2, 0);   // interleaved even rows
    wsplitT<<<dim3(88, 32), 256>>>(w3, w13Th, w13Tl, 1024, 2816, 2, 1);   // interleaved odd rows
    wsplitT<<<dim3(32, 32), 256>>>(wkm, wkvmTh, wkvmTl, 1024, 1024, 1, 0);
    wsplitT<<<dim3(32, 32), 256>>>(wvm, wkvmTh + 1024 * 1024, wkvmTl + 1024 * 1024, 1024, 1024, 1, 0);
    wsplitT<<<dim3(32, 32), 256>>>(wm, wmTh, wmTl, 1024, 1024, 1, 0);
    wsplitT<<<dim3(32, 88), 256>>>(w2, w2Th, w2Tl, 2816, 1024, 1, 0);
    wsplitT<<<dim3(32, 32), 256>>>(wo, woTh, woTl, 1024, 1024, 1, 0);
    asplit<<<8192, 256>>>(x, xh, xl, B_ * S_ * D_ / 4);
    init_om_split<<<4096, 256>>>(om0);

    // ---- batched x-branch: fused GEMM + rope/scatter (mode 4) ----
    gemm_hs<<<dim3(48, 64), 256, HSM_BYTES>>>(xh, xl, wqkvTh, wqkvTl, nullptr, 3072, 1024, 4,
                                              fcos, fsin, qall, kxall, vxall);

    const size_t stepSz = (size_t)B_ * H_ * M_ * HD_;
    for (int s = 0; s < NSTEP; s++) {
        gemm_hs<<<dim3(16, 8), 256, HSM_BYTES>>>(omh, oml, wmTh, wmTl, om2, 1024, 1024, 0,
                                                 nullptr, nullptr, nullptr, nullptr, nullptr);
        rmsnorm_split<<<1024, 256>>>(om2, ffnw, th, tl);
        gemm_hs<<<dim3(88, 8), 256, HSM_BYTES>>>(th, tl, w13Th, w13Tl, nullptr, 5632, 1024, 2,
                                                 nullptr, nullptr, gh, gl, nullptr);
        gemm_hs<<<dim3(16, 8), 256, HSM_BYTES>>>(gh, gl, w2Th, w2Tl, om2, 1024, 2816, 1,
                                                 nullptr, nullptr, nullptr, nullptr, nullptr);
        rmsnorm_split<<<1024, 256>>>(om2, memw, om3h, om3l);
        gemm_hs<<<dim3(32, 8), 256, HSM_BYTES>>>(om3h, om3l, wkvmTh, wkvmTl, nullptr, 2048, 1024, 3,
                                                 fcos, fsin, kmem, vmem, nullptr);
        attn2<<<dim3(B_ * H_, 8), 128>>>(qall + s * stepSz, kxall + s * stepSz,
                                         vxall + s * stepSz, s * M_);
    }

    // ---- final projection ----
    gemm_hs<<<dim3(16, 64), 256, HSM_BYTES>>>(outh, outl, woTh, woTl, outp, 1024, 1024, 0,
                                              nullptr, nullptr, nullptr, nullptr, nullptr);
}

// round 15
// speedup vs baseline: 1.5136x; 1.2882x over previous
#include <cuda_runtime.h>
#include <cuda_fp16.h>
#include <stdint.h>
#include <math.h>

#define B_ 2
#define S_ 4096
#define D_ 1024
#define H_ 16
#define HD_ 64
#define M_ 512
#define L_ 1024
#define HID_ 2816
#define NSTEP 8

// ---------------- scratch (static device globals; no allocs) ----------------
// weights: transposed, split fp16 hi / scaled-lo, layout [N][K]
__device__ __align__(16) __half g_wqkvTh[3*D_*D_], g_wqkvTl[3*D_*D_];
__device__ __align__(16) __half g_w13Th [2*HID_*D_], g_w13Tl [2*HID_*D_]; // interleaved rows
__device__ __align__(16) __half g_wkvmTh[2*D_*D_], g_wkvmTl[2*D_*D_];
__device__ __align__(16) __half g_wmTh  [D_*D_],  g_wmTl  [D_*D_];
__device__ __align__(16) __half g_w2Th  [D_*HID_], g_w2Tl [D_*HID_];
__device__ __align__(16) __half g_woTh  [D_*D_],  g_woTl  [D_*D_];
// activations: plain fp16 (hi only)
__device__ __align__(16) __half g_xh [B_*S_*D_];
__device__ __align__(16) __half g_omh[B_*M_*D_];
__device__ __align__(16) __half g_th [B_*M_*D_];
__device__ __align__(16) __half g_om3h[B_*M_*D_];
__device__ __align__(16) __half g_gh [B_*M_*HID_];
__device__ __align__(16) __half g_outh[B_*S_*D_];
__device__ float g_qall [NSTEP*B_*H_*M_*HD_];
__device__ float g_kxall[NSTEP*B_*H_*M_*HD_];
__device__ float g_vxall[NSTEP*B_*H_*M_*HD_];
__device__ float g_om2  [B_*M_*D_];
__device__ float g_kmem [B_*H_*M_*HD_], g_vmem[B_*H_*M_*HD_];

// ---------------- helpers ----------------------------------------------------
__device__ __forceinline__ void splith(float v, __half& h, __half& l) {
    h = __float2half_rn(v);
    l = __float2half_rn((v - __half2float(h)) * 2048.0f);
}

__device__ __forceinline__ void hmma(float* c, const uint32_t* a, const uint32_t* b)
{
    asm volatile("mma.sync.aligned.m16n8k16.row.col.f32.f16.f16.f32 "
                 "{%0,%1,%2,%3}, {%4,%5,%6,%7}, {%8,%9}, {%0,%1,%2,%3};"
                 : "+f"(c[0]), "+f"(c[1]), "+f"(c[2]), "+f"(c[3])
                 : "r"(a[0]), "r"(a[1]), "r"(a[2]), "r"(a[3]), "r"(b[0]), "r"(b[1]));
}

__device__ __forceinline__ void cpa16(uint8_t* dst, const void* src) {
    unsigned d = (unsigned)__cvta_generic_to_shared(dst);
    asm volatile("cp.async.cg.shared.global [%0], [%1], 16;" :: "r"(d), "l"(src));
}

__device__ __forceinline__ void ldm4(uint32_t* r, uint32_t addr) {
    asm volatile("ldmatrix.sync.aligned.m8n8.x4.shared.b16 {%0,%1,%2,%3}, [%4];"
                 : "=r"(r[0]), "=r"(r[1]), "=r"(r[2]), "=r"(r[3]) : "r"(addr));
}

// ---------------- fp16 GEMM, weights split (2 mma/tile) ----------------------
// C[M,Ntot] = Ah @ (Bh + Bl/2048)^T
// CTA tile 128x64, BK=32, 256 threads (8 warps 4x2), warp tile 32x32, 3-stage.
// MODE: 0 plain store | 1 accum | 2 silu-pair->gh | 3 kvm rope/scatter
//       4 xqkv rope/scatter (per-step layout)
#define HBM 128
#define HBN 64
#define HBK 32
#define ROWB 80
#define STG_A  0
#define STG_BH 10240
#define STG_BL 15360
#define STG_SZ 20480
#define HSM_BYTES (3 * STG_SZ)

template<int MODE>
__global__ void __launch_bounds__(256, 2)
gemm_hs(const __half* __restrict__ Ah,
        const __half* __restrict__ Bh, const __half* __restrict__ Bl,
        float* __restrict__ C, int Ntot, int K,
        const float* __restrict__ fcos, const float* __restrict__ fsin,
        void* p0, void* p1, void* p2)
{
    extern __shared__ uint8_t dyn[];
    const uint32_t sb = (uint32_t)__cvta_generic_to_shared(dyn);
    const int tid = threadIdx.x, lane = tid & 31, wid = tid >> 5;
    const int grp = lane >> 2, qk = lane & 3;
    const int wm = (wid >> 1) * 32, wn = (wid & 1) * 32;
    const int bm0 = blockIdx.y * HBM, bn0 = blockIdx.x * HBN;

    const int aRow = (lane & 7) + ((lane >> 3) & 1) * 8;
    const int aCol = ((lane >> 4) & 1) * 16;
    const int bRow = (lane & 7) + ((lane >> 4) & 1) * 8;
    const int bCol = ((lane >> 3) & 1) * 16;

    float acc0[2][4][4], acc1[2][4][4];
#pragma unroll
    for (int i = 0; i < 2; i++)
#pragma unroll
        for (int j = 0; j < 4; j++)
#pragma unroll
            for (int e = 0; e < 4; e++) { acc0[i][j][e] = 0.f; acc1[i][j][e] = 0.f; }

    auto issue = [&](int ci) {
        int p = ci % 3;
        int k0 = ci * HBK;
        uint8_t* dA  = dyn + p * STG_SZ + STG_A;
        uint8_t* dBh = dyn + p * STG_SZ + STG_BH;
        uint8_t* dBl = dyn + p * STG_SZ + STG_BL;
#pragma unroll
        for (int i = 0; i < 2; i++) {
            int idx = tid + i * 256;            // 512 chunks of 16B (A)
            int row = idx >> 2, c16 = idx & 3;
            size_t go = (size_t)(bm0 + row) * K + k0 + c16 * 8;
            cpa16(dA + row * ROWB + c16 * 16, Ah + go);
        }
        {
            int row = tid >> 2, c16 = tid & 3;  // 256 chunks (B)
            size_t go = (size_t)(bn0 + row) * K + k0 + c16 * 8;
            cpa16(dBh + row * ROWB + c16 * 16, Bh + go);
            cpa16(dBl + row * ROWB + c16 * 16, Bl + go);
        }
        asm volatile("cp.async.commit_group;");
    };

    const int nch = K / HBK;
    issue(0);
    if (nch > 1) issue(1);

    for (int st = 0; st < nch; st++) {
        if (st + 1 < nch) {
            asm volatile("cp.async.wait_group 1;");
        } else {
            asm volatile("cp.async.wait_group 0;");
        }
        __syncthreads();
        if (st + 2 < nch) issue(st + 2);

        int p = st % 3;
        uint32_t base = sb + p * STG_SZ;
#pragma unroll
        for (int s16 = 0; s16 < 2; s16++) {
            const int cb0 = s16 * 32;
            uint32_t ah[2][4], bh[4][2], bl[4][2];
#pragma unroll
            for (int mt = 0; mt < 2; mt++) {
                uint32_t ad = base + STG_A + (wm + mt * 16 + aRow) * ROWB + cb0 + aCol;
                ldm4(ah[mt], ad);
            }
#pragma unroll
            for (int g = 0; g < 2; g++) {
                uint32_t tmp[4];
                uint32_t bd = base + STG_BH + (wn + g * 16 + bRow) * ROWB + cb0 + bCol;
                ldm4(tmp, bd);
                bh[2 * g][0] = tmp[0]; bh[2 * g][1] = tmp[1];
                bh[2 * g + 1][0] = tmp[2]; bh[2 * g + 1][1] = tmp[3];
                ldm4(tmp, bd + (STG_BL - STG_BH));
                bl[2 * g][0] = tmp[0]; bl[2 * g][1] = tmp[1];
                bl[2 * g + 1][0] = tmp[2]; bl[2 * g + 1][1] = tmp[3];
            }
#pragma unroll
            for (int mt = 0; mt < 2; mt++)
#pragma unroll
                for (int nt = 0; nt < 4; nt++) {
                    hmma(acc0[mt][nt], ah[mt], bh[nt]);
                    hmma(acc1[mt][nt], ah[mt], bl[nt]);
                }
        }
    }

    const float isc = 4.8828125e-4f;   // 1/2048

    auto epi = [&](int r, int c, float u0, float u1) {
        if (MODE == 0) {
            *(float2*)(C + (size_t)r * Ntot + c) = make_float2(u0, u1);
        } else if (MODE == 1) {
            float2* p = (float2*)(C + (size_t)r * Ntot + c);
            float2 o = *p; o.x += u0; o.y += u1; *p = o;
        } else if (MODE == 2) {
            int n = c >> 1;
            float g = u0 / (1.f + __expf(-u0)) * u1;
            ((__half*)p0)[(size_t)r * HID_ + n] = __float2half_rn(g);
        } else if (MODE == 3) {
            int b = r >> 9, i = r & 511;
            if (c < 1024) {
                int h = c >> 6, j = (c & 63) >> 1;
                float cs = fcos[i * 32 + j], sn = fsin[i * 32 + j];
                float2 o = make_float2(u0 * cs - u1 * sn, u0 * sn + u1 * cs);
                *(float2*)((float*)p0 + (((size_t)(b * 16 + h) * 512 + i) * 64 + 2 * j)) = o;
            } else {
                int cc = c - 1024;
                int h = cc >> 6, d = cc & 63;
                *(float2*)((float*)p1 + (((size_t)(b * 16 + h) * 512 + i) * 64 + d)) = make_float2(u0, u1);
            }
        } else {  // MODE 4
            int b = r >> 12, rem = r & 4095, s = rem >> 9, i = rem & 511;
            size_t so = (size_t)s * (B_ * H_ * M_ * HD_);
            if (c < 2048) {
                int cc = (c < 1024) ? c : c - 1024;
                int h = cc >> 6, j = (cc & 63) >> 1;
                int pos = M_ + i;
                float cs = fcos[pos * 32 + j], sn = fsin[pos * 32 + j];
                float2 o = make_float2(u0 * cs - u1 * sn, u0 * sn + u1 * cs);
                float* dst = (c < 1024) ? (float*)p0 : (float*)p1;
                *(float2*)(dst + so + (((size_t)(b * 16 + h) * 512 + i) * 64 + 2 * j)) = o;
            } else {
                int cc = c - 2048;
                int h = cc >> 6, d = cc & 63;
                *(float2*)((float*)p2 + so + (((size_t)(b * 16 + h) * 512 + i) * 64 + d)) = make_float2(u0, u1);
            }
        }
    };

#pragma unroll
    for (int mt = 0; mt < 2; mt++) {
        int r0 = bm0 + wm + mt * 16 + grp;
#pragma unroll
        for (int nt = 0; nt < 4; nt++) {
            int c0 = bn0 + wn + nt * 8 + 2 * qk;
            float v0 = acc0[mt][nt][0] + acc1[mt][nt][0] * isc;
            float v1 = acc0[mt][nt][1] + acc1[mt][nt][1] * isc;
            float v2 = acc0[mt][nt][2] + acc1[mt][nt][2] * isc;
            float v3 = acc0[mt][nt][3] + acc1[mt][nt][3] * isc;
            epi(r0, c0, v0, v1);
            epi(r0 + 8, c0, v2, v3);
        }
    }
}

// ---------------- weight transpose + split: w[K][N] -> out[n*rmul+roff][K] ---
__global__ void __launch_bounds__(256) wsplitT(const float* __restrict__ w,
                                               __half* __restrict__ bh,
                                               __half* __restrict__ bl,
                                               int K, int N, int rmul, int roff)
{
    __shared__ float t[32][33];
    int n0 = blockIdx.x * 32, k0 = blockIdx.y * 32;
    int tx = threadIdx.x & 31, ty = threadIdx.x >> 5;
#pragma unroll
    for (int i = 0; i < 4; i++)
        t[ty + i * 8][tx] = w[(size_t)(k0 + ty + i * 8) * N + n0 + tx];
    __syncthreads();
#pragma unroll
    for (int i = 0; i < 4; i++) {
        int nn = ty + i * 8;
        float v = t[tx][nn];
        __half h, l;
        splith(v, h, l);
        size_t drow = (size_t)(n0 + nn) * rmul + roff;
        bh[drow * K + k0 + tx] = h;
        bl[drow * K + k0 + tx] = l;
    }
}

// ---------------- activation fp16 cast (no transpose) ------------------------
__global__ void __launch_bounds__(256) asplit(const float* __restrict__ in,
                                              __half* __restrict__ oh, int n4)
{
    int i = blockIdx.x * 256 + threadIdx.x;
    if (i >= n4) return;
    float4 v = ((const float4*)in)[i];
    ((__half2*)oh)[i * 2]     = __halves2half2(__float2half_rn(v.x), __float2half_rn(v.y));
    ((__half2*)oh)[i * 2 + 1] = __halves2half2(__float2half_rn(v.z), __float2half_rn(v.w));
}

__global__ void __launch_bounds__(256) init_om_split(const float* __restrict__ om0)
{
    int t = blockIdx.x * 256 + threadIdx.x;
    int d = t & 1023;
    int i = (t >> 10) & 511;
    g_omh[t] = __float2half_rn(om0[i * 1024 + d]);
}

// ---------------- rmsnorm -> fp16 --------------------------------------------
__global__ void __launch_bounds__(256) rmsnorm_split(const float* __restrict__ in,
                                                     const float* __restrict__ w,
                                                     __half* __restrict__ oh)
{
    const int row = blockIdx.x;
    const int t = threadIdx.x;
    float4 v = ((const float4*)(in + (size_t)row * D_))[t];
    float ss = v.x * v.x + v.y * v.y + v.z * v.z + v.w * v.w;
#pragma unroll
    for (int o = 16; o; o >>= 1) ss += __shfl_xor_sync(0xffffffffu, ss, o);
    __shared__ float sred[8];
    if ((t & 31) == 0) sred[t >> 5] = ss;
    __syncthreads();
    float tot = 0.f;
#pragma unroll
    for (int i = 0; i < 8; i++) tot += sred[i];
    float rs = rsqrtf(tot * (1.0f / (float)D_) + 1e-5f);
    float4 wv = ((const float4*)w)[t];
    __half2* ph = (__half2*)(oh + (size_t)row * D_);
    ph[t * 2]     = __halves2half2(__float2half_rn(v.x * rs * wv.x), __float2half_rn(v.y * rs * wv.y));
    ph[t * 2 + 1] = __halves2half2(__float2half_rn(v.z * rs * wv.z), __float2half_rn(v.w * rs * wv.w));
}

// ---------------- fused causal attention (x queries only) --------------------
__global__ void __launch_bounds__(128) attn2(const float* __restrict__ Qs,
                                             const float* __restrict__ Kx,
                                             const float* __restrict__ Vx,
                                             int stepOff)
{
    __shared__ float Ksh[64 * 72];
    __shared__ float Vsh[64 * 72];
    const int bh = blockIdx.x;
    const int by = blockIdx.y;
    const int b = bh >> 4, h = bh & 15;
    const int tid = threadIdx.x;
    const int rl = tid >> 1;
    const int half = tid & 1;
    const int off = half * 36;
    const int qrow = by * 64 + rl;

    const float* qp = Qs + ((size_t)bh * 512 + qrow) * 64 + half * 32;
    float q[32];
#pragma unroll
    for (int d = 0; d < 32; d += 4) {
        float4 v = *(const float4*)(qp + d);
        q[d] = v.x; q[d + 1] = v.y; q[d + 2] = v.z; q[d + 3] = v.w;
    }
    float O[32];
#pragma unroll
    for (int d = 0; d < 32; d++) O[d] = 0.f;
    float m = -1e30f, l = 0.f;

    const int nkt = 9 + by;
    for (int kt = 0; kt < nkt; kt++) {
        const float* ksrc = (kt < 8) ? (g_kmem + ((size_t)bh * 512 + kt * 64) * 64)
                                     : (Kx + ((size_t)bh * 512 + (kt - 8) * 64) * 64);
        const float* vsrc = (kt < 8) ? (g_vmem + ((size_t)bh * 512 + kt * 64) * 64)
                                     : (Vx + ((size_t)bh * 512 + (kt - 8) * 64) * 64);
        __syncthreads();
#pragma unroll
        for (int i = 0; i < 8; i++) {
            int idx = i * 128 + tid;
            int row = idx >> 4, c4 = idx & 15;
            int dst = row * 72 + c4 * 4 + (c4 >= 8 ? 4 : 0);
            *(float4*)(Ksh + dst) = ((const float4*)ksrc)[idx];
            *(float4*)(Vsh + dst) = ((const float4*)vsrc)[idx];
        }
        __syncthreads();
        const bool diag = (kt == 8 + by);
#pragma unroll 1
        for (int c = 0; c < 4; c++) {
            float sreg[16];
            float mt = -1e30f;
#pragma unroll
            for (int j = 0; j < 16; j++) {
                const float* kr = Ksh + (c * 16 + j) * 72 + off;
                float p = 0.f;
#pragma unroll
                for (int d = 0; d < 32; d += 4) {
                    float4 k4 = *(const float4*)(kr + d);
                    p += q[d] * k4.x + q[d + 1] * k4.y + q[d + 2] * k4.z + q[d + 3] * k4.w;
                }
                p += __shfl_xor_sync(0xffffffffu, p, 1);
                float sj = p * 0.125f;
                if (diag && (c * 16 + j) > rl) sj = -1e30f;
                sreg[j] = sj;
                mt = fmaxf(mt, sj);
            }
            float mnew = fmaxf(m, mt);
            float corr = __expf(m - mnew);
            l *= corr;
#pragma unroll
            for (int d = 0; d < 32; d++) O[d] *= corr;
#pragma unroll
            for (int j = 0; j < 16; j++) {
                float pj = __expf(sreg[j] - mnew);
                l += pj;
                const float* vr = Vsh + (c * 16 + j) * 72 + off;
#pragma unroll
                for (int d = 0; d < 32; d += 4) {
                    float4 v4 = *(const float4*)(vr + d);
                    O[d]     += pj * v4.x;
                    O[d + 1] += pj * v4.y;
                    O[d + 2] += pj * v4.z;
                    O[d + 3] += pj * v4.w;
                }
            }
            m = mnew;
        }
    }

    float inv = 1.0f / l;
    size_t o1 = ((size_t)b * S_ + stepOff + qrow) * D_ + h * 64 + half * 32;
    size_t o2 = ((size_t)(b * 512 + qrow)) * D_ + h * 64 + half * 32;
#pragma unroll
    for (int d = 0; d < 32; d += 2) {
        __half2 hh = __halves2half2(__float2half_rn(O[d] * inv),
                                    __float2half_rn(O[d + 1] * inv));
        *(__half2*)(g_outh + o1 + d) = hh;
        *(__half2*)(g_omh + o2 + d) = hh;
    }
}

// ---------------- host driver ------------------------------------------------
static void* symp(const void* s) { void* p; cudaGetSymbolAddress(&p, s); return p; }

extern "C" void kernel_launch(void* const* d_in, const int* in_sizes, int n_in,
                              void* d_out, int out_size)
{
    (void)in_sizes; (void)n_in; (void)out_size;
    const float* x    = (const float*)d_in[0];
    const float* fcos = (const float*)d_in[1];
    const float* fsin = (const float*)d_in[2];
    const float* wq   = (const float*)d_in[3];
    const float* wk   = (const float*)d_in[4];
    const float* wv   = (const float*)d_in[5];
    const float* wo   = (const float*)d_in[6];
    const float* wm   = (const float*)d_in[7];
    const float* wkm  = (const float*)d_in[8];
    const float* wvm  = (const float*)d_in[9];
    const float* w1   = (const float*)d_in[10];
    const float* w3   = (const float*)d_in[11];
    const float* w2   = (const float*)d_in[12];
    const float* ffnw = (const float*)d_in[13];
    const float* memw = (const float*)d_in[14];
    const float* om0  = (const float*)d_in[15];
    float* outp = (float*)d_out;

    static bool attrDone = false;
    if (!attrDone) {
        cudaFuncSetAttribute(gemm_hs<0>, cudaFuncAttributeMaxDynamicSharedMemorySize, HSM_BYTES);
        cudaFuncSetAttribute(gemm_hs<1>, cudaFuncAttributeMaxDynamicSharedMemorySize, HSM_BYTES);
        cudaFuncSetAttribute(gemm_hs<2>, cudaFuncAttributeMaxDynamicSharedMemorySize, HSM_BYTES);
        cudaFuncSetAttribute(gemm_hs<3>, cudaFuncAttributeMaxDynamicSharedMemorySize, HSM_BYTES);
        cudaFuncSetAttribute(gemm_hs<4>, cudaFuncAttributeMaxDynamicSharedMemorySize, HSM_BYTES);
        attrDone = true;
    }

    __half *wqkvTh = (__half*)symp(g_wqkvTh), *wqkvTl = (__half*)symp(g_wqkvTl);
    __half *w13Th = (__half*)symp(g_w13Th), *w13Tl = (__half*)symp(g_w13Tl);
    __half *wkvmTh = (__half*)symp(g_wkvmTh), *wkvmTl = (__half*)symp(g_wkvmTl);
    __half *wmTh = (__half*)symp(g_wmTh), *wmTl = (__half*)symp(g_wmTl);
    __half *w2Th = (__half*)symp(g_w2Th), *w2Tl = (__half*)symp(g_w2Tl);
    __half *woTh = (__half*)symp(g_woTh), *woTl = (__half*)symp(g_woTl);
    __half *xh = (__half*)symp(g_xh);
    __half *omh = (__half*)symp(g_omh);
    __half *th = (__half*)symp(g_th);
    __half *om3h = (__half*)symp(g_om3h);
    __half *gh = (__half*)symp(g_gh);
    __half *outh = (__half*)symp(g_outh);
    float *qall = (float*)symp(g_qall), *kxall = (float*)symp(g_kxall), *vxall = (float*)symp(g_vxall);
    float *om2 = (float*)symp(g_om2);
    float *kmem = (float*)symp(g_kmem), *vmem = (float*)symp(g_vmem);

    // ---- weight transpose+split / input cast (per launch) ----
    wsplitT<<<dim3(32, 32), 256>>>(wq, wqkvTh, wqkvTl, 1024, 1024, 1, 0);
    wsplitT<<<dim3(32, 32), 256>>>(wk, wqkvTh + 1024 * 1024, wqkvTl + 1024 * 1024, 1024, 1024, 1, 0);
    wsplitT<<<dim3(32, 32), 256>>>(wv, wqkvTh + 2048 * 1024, wqkvTl + 2048 * 1024, 1024, 1024, 1, 0);
    wsplitT<<<dim3(88, 32), 256>>>(w1, w13Th, w13Tl, 1024, 2816, 2, 0);
    wsplitT<<<dim3(88, 32), 256>>>(w3, w13Th, w13Tl, 1024, 2816, 2, 1);
    wsplitT<<<dim3(32, 32), 256>>>(wkm, wkvmTh, wkvmTl, 1024, 1024, 1, 0);
    wsplitT<<<dim3(32, 32), 256>>>(wvm, wkvmTh + 1024 * 1024, wkvmTl + 1024 * 1024, 1024, 1024, 1, 0);
    wsplitT<<<dim3(32, 32), 256>>>(wm, wmTh, wmTl, 1024, 1024, 1, 0);
    wsplitT<<<dim3(32, 88), 256>>>(w2, w2Th, w2Tl, 2816, 1024, 1, 0);
    wsplitT<<<dim3(32, 32), 256>>>(wo, woTh, woTl, 1024, 1024, 1, 0);
    asplit<<<8192, 256>>>(x, xh, B_ * S_ * D_ / 4);
    init_om_split<<<4096, 256>>>(om0);

    // ---- batched x-branch: fused GEMM + rope/scatter ----
    gemm_hs<4><<<dim3(48, 64), 256, HSM_BYTES>>>(xh, wqkvTh, wqkvTl, nullptr, 3072, 1024,
                                                 fcos, fsin, qall, kxall, vxall);

    const size_t stepSz = (size_t)B_ * H_ * M_ * HD_;
    for (int s = 0; s < NSTEP; s++) {
        gemm_hs<0><<<dim3(16, 8), 256, HSM_BYTES>>>(omh, wmTh, wmTl, om2, 1024, 1024,
                                                    nullptr, nullptr, nullptr, nullptr, nullptr);
        rmsnorm_split<<<1024, 256>>>(om2, ffnw, th);
        gemm_hs<2><<<dim3(88, 8), 256, HSM_BYTES>>>(th, w13Th, w13Tl, nullptr, 5632, 1024,
                                                    nullptr, nullptr, gh, nullptr, nullptr);
        gemm_hs<1><<<dim3(16, 8), 256, HSM_BYTES>>>(gh, w2Th, w2Tl, om2, 1024, 2816,
                                                    nullptr, nullptr, nullptr, nullptr, nullptr);
        rmsnorm_split<<<1024, 256>>>(om2, memw, om3h);
        gemm_hs<3><<<dim3(32, 8), 256, HSM_BYTES>>>(om3h, wkvmTh, wkvmTl, nullptr, 2048, 1024,
                                                    fcos, fsin, kmem, vmem, nullptr);
        attn2<<<dim3(B_ * H_, 8), 128>>>(qall + s * stepSz, kxall + s * stepSz,
                                         vxall + s * stepSz, s * M_);
    }

    // ---- final projection ----
    gemm_hs<0><<<dim3(16, 64), 256, HSM_BYTES>>>(outh, woTh, woTl, outp, 1024, 1024,
                                                 nullptr, nullptr, nullptr, nullptr, nullptr);
}